// round 8
// baseline (speedup 1.0000x reference)
#include <cuda_runtime.h>

#define N_NODES 50000
#define E_EDGES 800000
#define DIM     128
#define G_GRAPHS 128
#define C_CLASSES 10
#define BM 64                      // GEMM rows per block
#define SMP 132                    // padded smem row stride (floats)

// Scratch (device globals: no allocation allowed)
__device__ float g_bufA[N_NODES * DIM];
__device__ float g_bufB[N_NODES * DIM];
__device__ float g_rel [N_NODES * DIM];
__device__ float g_pool[G_GRAPHS * DIM];
__device__ float g_cnt [G_GRAPHS];
// CSR scratch (built once per launch; edge_index constant across layers)
__device__ int g_deg   [N_NODES];
__device__ int g_rowptr[N_NODES + 1];
__device__ int g_cursor[N_NODES];
__device__ int g_csrc  [E_EDGES];

typedef unsigned long long u64;

// f32x2 packed helpers (sm_103a; PTX-only, no C++ auto-fuse)
#define FMA2(acc, a, b) \
    asm("fma.rn.f32x2 %0, %1, %2, %0;" : "+l"(acc) : "l"(a), "l"(b))
#define ADD2(out, a, b) \
    asm("add.rn.f32x2 %0, %1, %2;" : "=l"(out) : "l"(a), "l"(b))
#define PACKDUP(out, x) \
    asm("mov.b64 %0, {%1, %1};" : "=l"(out) : "r"(__float_as_uint(x)))

// ---------------------------------------------------------------------------
// Merged GEMM: one block handles a 64-row slab of A (N x 128) and computes
//   phase 0: g_rel[n,o] = sum_k act(A[n,k]) * Wrel[o,k]
//   phase 1: next[n,o]  = sum_k act(A[n,k]) * Wroot[o,k] + bias[o]
// A slab loaded (and ReLU'd) ONCE; W reloaded per phase. Inner loop uses
// packed fma.rn.f32x2 (2 flops/FMA-issue).
// ---------------------------------------------------------------------------
__global__ __launch_bounds__(256, 2)
void gemm2_kernel(const float* __restrict__ A,
                  const float* __restrict__ Wrel,
                  const float* __restrict__ Wroot,
                  const float* __restrict__ bias,
                  float* __restrict__ rel_out,
                  float* __restrict__ next_out,
                  int apply_relu)
{
    extern __shared__ float sm[];
    float* As = sm;                 // [BM][SMP]
    float* Ws = sm + BM * SMP;      // Wt[k][o] : [128][SMP]

    const int tid = threadIdx.x;
    const int m0  = blockIdx.x * BM;

    // --- load A slab (64 x 128) into As[r][k], relu folded, once ---
    {
        int r  = tid >> 2;              // 0..63
        int kb = (tid & 3) * 32;        // 0,32,64,96
        int row = m0 + r;
        if (row < N_NODES) {
            const float4* src = (const float4*)(A + (size_t)row * DIM + kb);
            float4* dst = (float4*)(As + r * SMP + kb);
            #pragma unroll
            for (int i = 0; i < 8; i++) {
                float4 v = src[i];
                if (apply_relu) {
                    v.x = fmaxf(v.x, 0.f); v.y = fmaxf(v.y, 0.f);
                    v.z = fmaxf(v.z, 0.f); v.w = fmaxf(v.w, 0.f);
                }
                dst[i] = v;
            }
        } else {
            float4 z = make_float4(0.f, 0.f, 0.f, 0.f);
            float4* dst = (float4*)(As + r * SMP + kb);
            #pragma unroll
            for (int i = 0; i < 8; i++) dst[i] = z;
        }
    }

    const int tx = tid & 15;            // output-col group: cols tx*8 .. +7
    const int ty = tid >> 4;            // row group: rows ty*4 .. +3

    #pragma unroll
    for (int phase = 0; phase < 2; phase++) {
        const float* W = phase ? Wroot : Wrel;

        __syncthreads();   // protect Ws from previous phase's readers / As fill
        // --- load W (128 x 128) transposed into Ws[k][o] ---
        {
            int o  = tid >> 1;              // 0..127
            int kb = (tid & 1) * 64;        // 0,64
            const float4* src = (const float4*)(W + (size_t)o * DIM + kb);
            #pragma unroll
            for (int i = 0; i < 16; i++) {
                float4 v = src[i];
                int k = kb + i * 4;
                Ws[(k + 0) * SMP + o] = v.x;
                Ws[(k + 1) * SMP + o] = v.y;
                Ws[(k + 2) * SMP + o] = v.z;
                Ws[(k + 3) * SMP + o] = v.w;
            }
        }
        __syncthreads();

        // acc2[i][j2]: row i, packed column pair j2 (cols tx*8+2*j2, +1)
        u64 acc2[4][4];
        #pragma unroll
        for (int i = 0; i < 4; i++)
            #pragma unroll
            for (int j = 0; j < 4; j++) acc2[i][j] = 0ULL;

        #pragma unroll 4
        for (int k = 0; k < 128; k++) {
            float a0 = As[(ty * 4 + 0) * SMP + k];
            float a1 = As[(ty * 4 + 1) * SMP + k];
            float a2 = As[(ty * 4 + 2) * SMP + k];
            float a3 = As[(ty * 4 + 3) * SMP + k];
            u64 A0, A1, A2, A3;
            PACKDUP(A0, a0); PACKDUP(A1, a1);
            PACKDUP(A2, a2); PACKDUP(A3, a3);
            ulonglong2 bA = *(const ulonglong2*)(Ws + k * SMP + tx * 8);
            ulonglong2 bB = *(const ulonglong2*)(Ws + k * SMP + tx * 8 + 4);
            FMA2(acc2[0][0], A0, bA.x); FMA2(acc2[0][1], A0, bA.y);
            FMA2(acc2[0][2], A0, bB.x); FMA2(acc2[0][3], A0, bB.y);
            FMA2(acc2[1][0], A1, bA.x); FMA2(acc2[1][1], A1, bA.y);
            FMA2(acc2[1][2], A1, bB.x); FMA2(acc2[1][3], A1, bB.y);
            FMA2(acc2[2][0], A2, bA.x); FMA2(acc2[2][1], A2, bA.y);
            FMA2(acc2[2][2], A2, bB.x); FMA2(acc2[2][3], A2, bB.y);
            FMA2(acc2[3][0], A3, bA.x); FMA2(acc2[3][1], A3, bA.y);
            FMA2(acc2[3][2], A3, bB.x); FMA2(acc2[3][3], A3, bB.y);
        }

        if (phase) {
            // bias add, packed
            ulonglong2 biasA = *(const ulonglong2*)(bias + tx * 8);
            ulonglong2 biasB = *(const ulonglong2*)(bias + tx * 8 + 4);
            #pragma unroll
            for (int i = 0; i < 4; i++) {
                ADD2(acc2[i][0], acc2[i][0], biasA.x);
                ADD2(acc2[i][1], acc2[i][1], biasA.y);
                ADD2(acc2[i][2], acc2[i][2], biasB.x);
                ADD2(acc2[i][3], acc2[i][3], biasB.y);
            }
        }

        float* outp = phase ? next_out : rel_out;
        #pragma unroll
        for (int i = 0; i < 4; i++) {
            int row = m0 + ty * 4 + i;
            if (row < N_NODES) {
                ulonglong2* dst =
                    (ulonglong2*)(outp + (size_t)row * DIM + tx * 8);
                ulonglong2 v0; v0.x = acc2[i][0]; v0.y = acc2[i][1];
                ulonglong2 v1; v1.x = acc2[i][2]; v1.y = acc2[i][3];
                dst[0] = v0;
                dst[1] = v1;
            }
        }
    }
}

// ---------------------------------------------------------------------------
// CSR build (once per launch): deg histogram -> exclusive scan -> fill
// ---------------------------------------------------------------------------
__global__ void deg_zero_kernel()
{
    int i = blockIdx.x * blockDim.x + threadIdx.x;
    if (i < N_NODES) g_deg[i] = 0;
}

__global__ void deg_hist_kernel(const int* __restrict__ ei)
{
    int e = blockIdx.x * blockDim.x + threadIdx.x;
    if (e < E_EDGES) atomicAdd(&g_deg[ei[E_EDGES + e]], 1);
}

// Single-block exclusive scan over g_deg -> g_rowptr (+ cursor copy).
__global__ __launch_bounds__(1024)
void scan_kernel()
{
    __shared__ int sh[1024];
    __shared__ int carry;
    if (threadIdx.x == 0) carry = 0;
    __syncthreads();
    for (int base = 0; base < N_NODES; base += 1024) {
        int i = base + threadIdx.x;
        int v = (i < N_NODES) ? g_deg[i] : 0;
        sh[threadIdx.x] = v;
        __syncthreads();
        #pragma unroll
        for (int off = 1; off < 1024; off <<= 1) {
            int t = (threadIdx.x >= off) ? sh[threadIdx.x - off] : 0;
            __syncthreads();
            sh[threadIdx.x] += t;
            __syncthreads();
        }
        int excl = sh[threadIdx.x] - v;
        int c = carry;
        if (i < N_NODES) {
            g_rowptr[i] = c + excl;
            g_cursor[i] = c + excl;
        }
        int total = sh[1023];
        __syncthreads();
        if (threadIdx.x == 0) carry = c + total;
        __syncthreads();
    }
    if (threadIdx.x == 0) g_rowptr[N_NODES] = carry;
}

__global__ void fill_kernel(const int* __restrict__ ei)
{
    int e = blockIdx.x * blockDim.x + threadIdx.x;
    if (e < E_EDGES) {
        int d = ei[E_EDGES + e];
        int pos = atomicAdd(&g_cursor[d], 1);
        g_csrc[pos] = ei[e];
    }
}

// ---------------------------------------------------------------------------
// Gather: one warp per dst node. next[d] += sum_{s in in(d)} rel[s].
// Atomic-free: each warp exclusively owns its 512B output row.
// ---------------------------------------------------------------------------
__global__ __launch_bounds__(256)
void gather_kernel(const float* __restrict__ rel,
                   float* __restrict__ next)
{
    int w    = (blockIdx.x * blockDim.x + threadIdx.x) >> 5;
    int lane = threadIdx.x & 31;
    if (w >= N_NODES) return;
    int beg = g_rowptr[w];
    int end = g_rowptr[w + 1];

    float4 acc = make_float4(0.f, 0.f, 0.f, 0.f);
    int i = beg;
    // 4-way batched loads for MLP
    for (; i + 4 <= end; i += 4) {
        int s0 = g_csrc[i + 0];
        int s1 = g_csrc[i + 1];
        int s2 = g_csrc[i + 2];
        int s3 = g_csrc[i + 3];
        float4 v0 = ((const float4*)(rel + (size_t)s0 * DIM))[lane];
        float4 v1 = ((const float4*)(rel + (size_t)s1 * DIM))[lane];
        float4 v2 = ((const float4*)(rel + (size_t)s2 * DIM))[lane];
        float4 v3 = ((const float4*)(rel + (size_t)s3 * DIM))[lane];
        acc.x += v0.x + v1.x + v2.x + v3.x;
        acc.y += v0.y + v1.y + v2.y + v3.y;
        acc.z += v0.z + v1.z + v2.z + v3.z;
        acc.w += v0.w + v1.w + v2.w + v3.w;
    }
    for (; i < end; i++) {
        int s = g_csrc[i];
        float4 v = ((const float4*)(rel + (size_t)s * DIM))[lane];
        acc.x += v.x; acc.y += v.y; acc.z += v.z; acc.w += v.w;
    }

    float4* p = (float4*)(next + (size_t)w * DIM) + lane;
    float4 o = *p;
    o.x += acc.x; o.y += acc.y; o.z += acc.z; o.w += acc.w;
    *p = o;
}

// ---------------------------------------------------------------------------
// Zero pool accumulators
// ---------------------------------------------------------------------------
__global__ void zero_kernel(float* __restrict__ pool, float* __restrict__ cnt)
{
    int i = blockIdx.x * blockDim.x + threadIdx.x;
    if (i < G_GRAPHS * DIM) pool[i] = 0.f;
    if (i < G_GRAPHS) cnt[i] = 0.f;
}

// ---------------------------------------------------------------------------
// Mean pool: batch (int32) is SORTED -> run-length accumulation. 128 threads
// per block (one per feature), 64 nodes per block. ReLU applied here.
// ---------------------------------------------------------------------------
__global__ __launch_bounds__(128)
void pool_kernel(const float* __restrict__ h,
                 const int* __restrict__ batch,
                 float* __restrict__ pool,
                 float* __restrict__ cnt)
{
    int f  = threadIdx.x;
    int n0 = blockIdx.x * 64;
    int n1 = n0 + 64;
    if (n1 > N_NODES) n1 = N_NODES;

    int cur = batch[n0];
    float acc = 0.f;
    for (int n = n0; n < n1; n++) {
        int b = batch[n];
        if (b != cur) {
            atomicAdd(&pool[cur * DIM + f], acc);
            acc = 0.f;
            cur = b;
        }
        acc += fmaxf(h[(size_t)n * DIM + f], 0.f);
    }
    atomicAdd(&pool[cur * DIM + f], acc);

    if (f == 0) {
        int c2 = batch[n0];
        float c = 0.f;
        for (int n = n0; n < n1; n++) {
            int b = batch[n];
            if (b != c2) { atomicAdd(&cnt[c2], c); c = 0.f; c2 = b; }
            c += 1.f;
        }
        atomicAdd(&cnt[c2], c);
    }
}

// ---------------------------------------------------------------------------
// Head: out[g,c] = (pool[g]/max(cnt,1)) . lin_w[c] + lin_b[c]
// ---------------------------------------------------------------------------
__global__ __launch_bounds__(128)
void final_kernel(const float* __restrict__ pool,
                  const float* __restrict__ cnt,
                  const float* __restrict__ lw,
                  const float* __restrict__ lb,
                  float* __restrict__ out)
{
    __shared__ float red[4];
    int g = blockIdx.x;
    int t = threadIdx.x;
    float c = fmaxf(cnt[g], 1.0f);
    float v = pool[g * DIM + t] / c;
    for (int cc = 0; cc < C_CLASSES; cc++) {
        float p = v * lw[cc * DIM + t];
        #pragma unroll
        for (int off = 16; off; off >>= 1)
            p += __shfl_down_sync(0xffffffffu, p, off);
        if ((t & 31) == 0) red[t >> 5] = p;
        __syncthreads();
        if (t == 0)
            out[g * C_CLASSES + cc] = red[0] + red[1] + red[2] + red[3] + lb[cc];
        __syncthreads();
    }
}

// ---------------------------------------------------------------------------
extern "C" void kernel_launch(void* const* d_in, const int* in_sizes, int n_in,
                              void* d_out, int out_size)
{
    const float* x     = (const float*)d_in[0];
    const int*   ei    = (const int*)d_in[1];      // int32 on device
    const int*   batch = (const int*)d_in[2];      // int32 on device
    const float* Wrel[4]  = {(const float*)d_in[3], (const float*)d_in[6],
                             (const float*)d_in[9], (const float*)d_in[12]};
    const float* brel[4]  = {(const float*)d_in[4], (const float*)d_in[7],
                             (const float*)d_in[10], (const float*)d_in[13]};
    const float* Wroot[4] = {(const float*)d_in[5], (const float*)d_in[8],
                             (const float*)d_in[11], (const float*)d_in[14]};
    const float* lin_w = (const float*)d_in[15];
    const float* lin_b = (const float*)d_in[16];
    float* out = (float*)d_out;

    float *bufA, *bufB, *rel, *pool, *cnt;
    cudaGetSymbolAddress((void**)&bufA, g_bufA);
    cudaGetSymbolAddress((void**)&bufB, g_bufB);
    cudaGetSymbolAddress((void**)&rel,  g_rel);
    cudaGetSymbolAddress((void**)&pool, g_pool);
    cudaGetSymbolAddress((void**)&cnt,  g_cnt);

    size_t smem = (size_t)(BM + 128) * SMP * sizeof(float);  // ~99 KB
    cudaFuncSetAttribute(gemm2_kernel, cudaFuncAttributeMaxDynamicSharedMemorySize,
                         (int)smem);

    // --- Build CSR once (edge_index identical for all layers) ---
    deg_zero_kernel<<<(N_NODES + 255) / 256, 256>>>();
    deg_hist_kernel<<<(E_EDGES + 255) / 256, 256>>>(ei);
    scan_kernel<<<1, 1024>>>();
    fill_kernel<<<(E_EDGES + 255) / 256, 256>>>(ei);

    int ggrid = (N_NODES + BM - 1) / BM;
    int gthblocks = (N_NODES * 32 + 255) / 256;   // one warp per dst node

    const float* h = x;
    for (int i = 0; i < 4; i++) {
        float* nxt = (i & 1) ? bufB : bufA;
        gemm2_kernel<<<ggrid, 256, smem>>>(h, Wrel[i], Wroot[i], brel[i],
                                           rel, nxt, i > 0);
        gather_kernel<<<gthblocks, 256>>>(rel, nxt);
        h = nxt;
    }

    zero_kernel<<<(G_GRAPHS * DIM + 255) / 256, 256>>>(pool, cnt);
    pool_kernel<<<(N_NODES + 63) / 64, 128>>>(h, batch, pool, cnt);
    final_kernel<<<G_GRAPHS, 128>>>(pool, cnt, lin_w, lin_b, out);
}

// round 10
// speedup vs baseline: 1.8475x; 1.8475x over previous
#include <cuda_runtime.h>
#include <cuda_bf16.h>
#include <cstdint>

#define N_NODES 50000
#define E_EDGES 800000
#define DIM     128
#define G_GRAPHS 128
#define C_CLASSES 10
#define TILE_M  128
#define SMP2    136                     // padded bf16 row stride (272 B)
#define TILE_ELEMS (TILE_M * SMP2)      // 17408 bf16
#define TILE_BYTES (TILE_ELEMS * 2)     // 34816 B

// ---------------------------------------------------------------------------
// Device scratch (no allocation allowed)
// ---------------------------------------------------------------------------
__device__ float g_bufA[N_NODES * DIM];
__device__ float g_bufB[N_NODES * DIM];
__device__ float g_rel [N_NODES * DIM];
__device__ float g_pool[G_GRAPHS * DIM];
__device__ float g_cnt [G_GRAPHS];
// CSR scratch
__device__ int g_deg   [N_NODES];
__device__ int g_rowptr[N_NODES + 1];
__device__ int g_cursor[N_NODES];
__device__ int g_csrc  [E_EDGES];
// Pre-converted W images, padded rows (SMP2), order per layer:
// [2*layer][0]=rel hi, [2*layer][1]=rel lo, [2*layer+1][0]=root hi, [1]=root lo
__device__ __nv_bfloat16 g_wimg[8][2][TILE_ELEMS];

// ---------------------------------------------------------------------------
// helpers
// ---------------------------------------------------------------------------
__device__ __forceinline__ uint32_t smem_u32(const void* p) {
    uint32_t a;
    asm("{ .reg .u64 t; cvta.to.shared.u64 t, %1; cvt.u32.u64 %0, t; }"
        : "=r"(a) : "l"(p));
    return a;
}

// split fp32 pair -> bf16 hi pair + bf16 lo pair (packed: first arg in low half)
__device__ __forceinline__ void split2(float a, float b, uint32_t& hi, uint32_t& lo) {
    asm("cvt.rn.bf16x2.f32 %0, %1, %2;" : "=r"(hi) : "f"(b), "f"(a));
    float ra = a - __uint_as_float(hi << 16);
    float rb = b - __uint_as_float(hi & 0xffff0000u);
    asm("cvt.rn.bf16x2.f32 %0, %1, %2;" : "=r"(lo) : "f"(rb), "f"(ra));
}

__device__ __forceinline__ void ldsm_x4(uint32_t& a0, uint32_t& a1,
                                        uint32_t& a2, uint32_t& a3, uint32_t addr) {
    asm volatile("ldmatrix.sync.aligned.m8n8.x4.shared.b16 {%0,%1,%2,%3}, [%4];"
                 : "=r"(a0), "=r"(a1), "=r"(a2), "=r"(a3) : "r"(addr));
}
__device__ __forceinline__ void ldsm_x2(uint32_t& b0, uint32_t& b1, uint32_t addr) {
    asm volatile("ldmatrix.sync.aligned.m8n8.x2.shared.b16 {%0,%1}, [%2];"
                 : "=r"(b0), "=r"(b1) : "r"(addr));
}
__device__ __forceinline__ void mma_bf16(float* c, uint32_t a0, uint32_t a1,
                                         uint32_t a2, uint32_t a3,
                                         uint32_t b0, uint32_t b1) {
    asm volatile("mma.sync.aligned.m16n8k16.row.col.f32.bf16.bf16.f32 "
                 "{%0,%1,%2,%3}, {%4,%5,%6,%7}, {%8,%9}, {%0,%1,%2,%3};"
                 : "+f"(c[0]), "+f"(c[1]), "+f"(c[2]), "+f"(c[3])
                 : "r"(a0), "r"(a1), "r"(a2), "r"(a3), "r"(b0), "r"(b1));
}

// ---------------------------------------------------------------------------
// W pre-convert: 8 blocks, one per (layer, mat). fp32 -> bf16 hi/lo, padded rows.
// ---------------------------------------------------------------------------
struct WPtrs { const float* p[8]; };

__global__ __launch_bounds__(256)
void w_convert_kernel(WPtrs wp)
{
    int b = blockIdx.x;
    const float* src = wp.p[b];
    __nv_bfloat16* hi_img = &g_wimg[b][0][0];
    __nv_bfloat16* lo_img = &g_wimg[b][1][0];
    int tid = threadIdx.x;
    #pragma unroll
    for (int it = 0; it < 16; it++) {
        int id = tid + it * 256;        // 0..4095 quads
        int r = id >> 5;
        int c = (id & 31) * 4;
        float4 v = *(const float4*)(src + r * DIM + c);
        uint32_t h0, l0, h1, l1;
        split2(v.x, v.y, h0, l0);
        split2(v.z, v.w, h1, l1);
        *(uint2*)(hi_img + r * SMP2 + c) = make_uint2(h0, h1);
        *(uint2*)(lo_img + r * SMP2 + c) = make_uint2(l0, l1);
    }
}

// ---------------------------------------------------------------------------
// HMMA GEMM pair: one block per 128-row slab of A.
//   rel[n,o]  = act(A)[n,:] . Wrel[o,:]
//   next[n,o] = act(A)[n,:] . Wroot[o,:] + bias[o]
// Split-bf16, 3 terms: Ahi*Whi + Ahi*Wlo + Alo*Whi (fp32 accum).
// smem tiles (bf16, padded SMP2): [0]=Ahi [1]=Alo [2]=Wrel_hi [3]=Wrel_lo
// [4]=Wroot_hi [5]=Wroot_lo   — tiles 2..5 are one contiguous copy from g_wimg.
// ---------------------------------------------------------------------------
__global__ __launch_bounds__(256, 1)
void gemm_mma_kernel(const float* __restrict__ A,
                     const float* __restrict__ bias,
                     float* __restrict__ rel_out,
                     float* __restrict__ next_out,
                     int layer, int apply_relu)
{
    extern __shared__ __align__(16) char sm[];
    __nv_bfloat16* tiles = (__nv_bfloat16*)sm;
    const uint32_t smb = smem_u32(sm);
    const int tid  = threadIdx.x;
    const int wid  = tid >> 5;
    const int lane = tid & 31;
    const int m0   = blockIdx.x * TILE_M;

    // --- copy 4 W tiles (contiguous in g_wimg) ---
    {
        const uint4* src = (const uint4*)&g_wimg[2 * layer][0][0];
        uint4* dst = (uint4*)(tiles + 2 * TILE_ELEMS);
        #pragma unroll
        for (int it = 0; it < 34; it++)
            dst[tid + it * 256] = src[tid + it * 256];   // 8704 uint4 total
    }

    // --- A convert: fp32 (+ReLU) -> bf16 hi/lo, padded rows ---
    {
        __nv_bfloat16* ahi = tiles;
        __nv_bfloat16* alo = tiles + TILE_ELEMS;
        #pragma unroll
        for (int it = 0; it < 16; it++) {
            int id = tid + it * 256;        // 0..4095 quads
            int r = id >> 5;
            int c = (id & 31) * 4;
            int row = m0 + r;
            float4 v = make_float4(0.f, 0.f, 0.f, 0.f);
            if (row < N_NODES) v = *(const float4*)(A + (size_t)row * DIM + c);
            if (apply_relu) {
                v.x = fmaxf(v.x, 0.f); v.y = fmaxf(v.y, 0.f);
                v.z = fmaxf(v.z, 0.f); v.w = fmaxf(v.w, 0.f);
            }
            uint32_t h0, l0, h1, l1;
            split2(v.x, v.y, h0, l0);
            split2(v.z, v.w, h1, l1);
            *(uint2*)(ahi + r * SMP2 + c) = make_uint2(h0, h1);
            *(uint2*)(alo + r * SMP2 + c) = make_uint2(l0, l1);
        }
    }
    __syncthreads();

    // per-lane ldmatrix base offsets
    const int li = lane & 15;
    // A: 16 rows (lane%16), k-halves by lane/16
    const uint32_t a_off = (uint32_t)((wid * 16 + li) * SMP2 * 2 + (lane >> 4) * 16);
    // B: 8 n-rows (li%8), k-halves by li/8
    const uint32_t b_off = (uint32_t)((li & 7) * SMP2 * 2 + (li >> 3) * 16);

    const uint32_t aHi = smb + a_off;
    const uint32_t aLo = smb + TILE_BYTES + a_off;

    const int grp = lane >> 2, q = lane & 3;
    const int row0 = m0 + wid * 16 + grp;

    #pragma unroll
    for (int phase = 0; phase < 2; phase++) {
        float acc[16][4];
        #pragma unroll
        for (int nb = 0; nb < 16; nb++)
            #pragma unroll
            for (int j = 0; j < 4; j++) acc[nb][j] = 0.f;

        const uint32_t wHi = smb + (2 + 2 * phase) * TILE_BYTES + b_off;
        const uint32_t wLo = wHi + TILE_BYTES;

        #pragma unroll
        for (int t = 0; t < 3; t++) {
            const uint32_t abase = (t == 2) ? aLo : aHi;
            const uint32_t wbase = (t == 1) ? wLo : wHi;
            #pragma unroll
            for (int ks = 0; ks < 8; ks++) {
                uint32_t a0, a1, a2, a3;
                ldsm_x4(a0, a1, a2, a3, abase + ks * 32);
                #pragma unroll
                for (int nb = 0; nb < 16; nb++) {
                    uint32_t b0, b1;
                    ldsm_x2(b0, b1, wbase + nb * 8 * SMP2 * 2 + ks * 32);
                    mma_bf16(acc[nb], a0, a1, a2, a3, b0, b1);
                }
            }
        }

        float* outp = phase ? next_out : rel_out;
        #pragma unroll
        for (int nb = 0; nb < 16; nb++) {
            int col = nb * 8 + q * 2;
            float c0 = acc[nb][0], c1 = acc[nb][1];
            float c2 = acc[nb][2], c3 = acc[nb][3];
            if (phase) {
                float bb0 = bias[col], bb1 = bias[col + 1];
                c0 += bb0; c1 += bb1; c2 += bb0; c3 += bb1;
            }
            if (row0 < N_NODES)
                *(float2*)(outp + (size_t)row0 * DIM + col) = make_float2(c0, c1);
            if (row0 + 8 < N_NODES)
                *(float2*)(outp + (size_t)(row0 + 8) * DIM + col) = make_float2(c2, c3);
        }
    }
}

// ---------------------------------------------------------------------------
// CSR build (once per launch)
// ---------------------------------------------------------------------------
__global__ void deg_zero_kernel()
{
    int i = blockIdx.x * blockDim.x + threadIdx.x;
    if (i < N_NODES) g_deg[i] = 0;
}

__global__ void deg_hist_kernel(const int* __restrict__ ei)
{
    int e = blockIdx.x * blockDim.x + threadIdx.x;
    if (e < E_EDGES) atomicAdd(&g_deg[ei[E_EDGES + e]], 1);
}

__global__ __launch_bounds__(1024)
void scan_kernel()
{
    __shared__ int sh[1024];
    __shared__ int carry;
    if (threadIdx.x == 0) carry = 0;
    __syncthreads();
    for (int base = 0; base < N_NODES; base += 1024) {
        int i = base + threadIdx.x;
        int v = (i < N_NODES) ? g_deg[i] : 0;
        sh[threadIdx.x] = v;
        __syncthreads();
        #pragma unroll
        for (int off = 1; off < 1024; off <<= 1) {
            int t = (threadIdx.x >= off) ? sh[threadIdx.x - off] : 0;
            __syncthreads();
            sh[threadIdx.x] += t;
            __syncthreads();
        }
        int excl = sh[threadIdx.x] - v;
        int c = carry;
        if (i < N_NODES) {
            g_rowptr[i] = c + excl;
            g_cursor[i] = c + excl;
        }
        int total = sh[1023];
        __syncthreads();
        if (threadIdx.x == 0) carry = c + total;
        __syncthreads();
    }
    if (threadIdx.x == 0) g_rowptr[N_NODES] = carry;
}

__global__ void fill_kernel(const int* __restrict__ ei)
{
    int e = blockIdx.x * blockDim.x + threadIdx.x;
    if (e < E_EDGES) {
        int d = ei[E_EDGES + e];
        int pos = atomicAdd(&g_cursor[d], 1);
        g_csrc[pos] = ei[e];
    }
}

// ---------------------------------------------------------------------------
// Gather: one warp per dst node (atomic-free). next[d] += sum rel[src].
// ---------------------------------------------------------------------------
__global__ __launch_bounds__(256)
void gather_kernel(const float* __restrict__ rel,
                   float* __restrict__ next)
{
    int w    = (blockIdx.x * blockDim.x + threadIdx.x) >> 5;
    int lane = threadIdx.x & 31;
    if (w >= N_NODES) return;
    int beg = g_rowptr[w];
    int end = g_rowptr[w + 1];

    float4 acc = make_float4(0.f, 0.f, 0.f, 0.f);
    int i = beg;
    for (; i + 4 <= end; i += 4) {
        int s0 = g_csrc[i + 0];
        int s1 = g_csrc[i + 1];
        int s2 = g_csrc[i + 2];
        int s3 = g_csrc[i + 3];
        float4 v0 = ((const float4*)(rel + (size_t)s0 * DIM))[lane];
        float4 v1 = ((const float4*)(rel + (size_t)s1 * DIM))[lane];
        float4 v2 = ((const float4*)(rel + (size_t)s2 * DIM))[lane];
        float4 v3 = ((const float4*)(rel + (size_t)s3 * DIM))[lane];
        acc.x += v0.x + v1.x + v2.x + v3.x;
        acc.y += v0.y + v1.y + v2.y + v3.y;
        acc.z += v0.z + v1.z + v2.z + v3.z;
        acc.w += v0.w + v1.w + v2.w + v3.w;
    }
    for (; i < end; i++) {
        int s = g_csrc[i];
        float4 v = ((const float4*)(rel + (size_t)s * DIM))[lane];
        acc.x += v.x; acc.y += v.y; acc.z += v.z; acc.w += v.w;
    }

    float4* p = (float4*)(next + (size_t)w * DIM) + lane;
    float4 o = *p;
    o.x += acc.x; o.y += acc.y; o.z += acc.z; o.w += acc.w;
    *p = o;
}

// ---------------------------------------------------------------------------
__global__ void zero_kernel(float* __restrict__ pool, float* __restrict__ cnt)
{
    int i = blockIdx.x * blockDim.x + threadIdx.x;
    if (i < G_GRAPHS * DIM) pool[i] = 0.f;
    if (i < G_GRAPHS) cnt[i] = 0.f;
}

__global__ __launch_bounds__(128)
void pool_kernel(const float* __restrict__ h,
                 const int* __restrict__ batch,
                 float* __restrict__ pool,
                 float* __restrict__ cnt)
{
    int f  = threadIdx.x;
    int n0 = blockIdx.x * 64;
    int n1 = n0 + 64;
    if (n1 > N_NODES) n1 = N_NODES;

    int cur = batch[n0];
    float acc = 0.f;
    for (int n = n0; n < n1; n++) {
        int b = batch[n];
        if (b != cur) {
            atomicAdd(&pool[cur * DIM + f], acc);
            acc = 0.f;
            cur = b;
        }
        acc += fmaxf(h[(size_t)n * DIM + f], 0.f);
    }
    atomicAdd(&pool[cur * DIM + f], acc);

    if (f == 0) {
        int c2 = batch[n0];
        float c = 0.f;
        for (int n = n0; n < n1; n++) {
            int b = batch[n];
            if (b != c2) { atomicAdd(&cnt[c2], c); c = 0.f; c2 = b; }
            c += 1.f;
        }
        atomicAdd(&cnt[c2], c);
    }
}

__global__ __launch_bounds__(128)
void final_kernel(const float* __restrict__ pool,
                  const float* __restrict__ cnt,
                  const float* __restrict__ lw,
                  const float* __restrict__ lb,
                  float* __restrict__ out)
{
    __shared__ float red[4];
    int g = blockIdx.x;
    int t = threadIdx.x;
    float c = fmaxf(cnt[g], 1.0f);
    float v = pool[g * DIM + t] / c;
    for (int cc = 0; cc < C_CLASSES; cc++) {
        float p = v * lw[cc * DIM + t];
        #pragma unroll
        for (int off = 16; off; off >>= 1)
            p += __shfl_down_sync(0xffffffffu, p, off);
        if ((t & 31) == 0) red[t >> 5] = p;
        __syncthreads();
        if (t == 0)
            out[g * C_CLASSES + cc] = red[0] + red[1] + red[2] + red[3] + lb[cc];
        __syncthreads();
    }
}

// ---------------------------------------------------------------------------
extern "C" void kernel_launch(void* const* d_in, const int* in_sizes, int n_in,
                              void* d_out, int out_size)
{
    const float* x     = (const float*)d_in[0];
    const int*   ei    = (const int*)d_in[1];
    const int*   batch = (const int*)d_in[2];
    const float* Wrel[4]  = {(const float*)d_in[3], (const float*)d_in[6],
                             (const float*)d_in[9], (const float*)d_in[12]};
    const float* brel[4]  = {(const float*)d_in[4], (const float*)d_in[7],
                             (const float*)d_in[10], (const float*)d_in[13]};
    const float* Wroot[4] = {(const float*)d_in[5], (const float*)d_in[8],
                             (const float*)d_in[11], (const float*)d_in[14]};
    const float* lin_w = (const float*)d_in[15];
    const float* lin_b = (const float*)d_in[16];
    float* out = (float*)d_out;

    float *bufA, *bufB, *rel, *pool, *cnt;
    cudaGetSymbolAddress((void**)&bufA, g_bufA);
    cudaGetSymbolAddress((void**)&bufB, g_bufB);
    cudaGetSymbolAddress((void**)&rel,  g_rel);
    cudaGetSymbolAddress((void**)&pool, g_pool);
    cudaGetSymbolAddress((void**)&cnt,  g_cnt);

    const int SM_TOTAL = 6 * TILE_BYTES;   // 208896 B
    cudaFuncSetAttribute(gemm_mma_kernel,
                         cudaFuncAttributeMaxDynamicSharedMemorySize, SM_TOTAL);

    // Pre-convert weights (hi/lo padded images), once per launch
    WPtrs wp;
    for (int i = 0; i < 4; i++) { wp.p[2 * i] = Wrel[i]; wp.p[2 * i + 1] = Wroot[i]; }
    w_convert_kernel<<<8, 256>>>(wp);

    // Build CSR once
    deg_zero_kernel<<<(N_NODES + 255) / 256, 256>>>();
    deg_hist_kernel<<<(E_EDGES + 255) / 256, 256>>>(ei);
    scan_kernel<<<1, 1024>>>();
    fill_kernel<<<(E_EDGES + 255) / 256, 256>>>(ei);

    int ggrid = (N_NODES + TILE_M - 1) / TILE_M;          // 391
    int gthblocks = (N_NODES * 32 + 255) / 256;

    const float* h = x;
    for (int i = 0; i < 4; i++) {
        float* nxt = (i & 1) ? bufB : bufA;
        gemm_mma_kernel<<<ggrid, 256, SM_TOTAL>>>(h, brel[i], rel, nxt, i, i > 0);
        gather_kernel<<<gthblocks, 256>>>(rel, nxt);
        h = nxt;
    }

    zero_kernel<<<(G_GRAPHS * DIM + 255) / 256, 256>>>(pool, cnt);
    pool_kernel<<<(N_NODES + 63) / 64, 128>>>(h, batch, pool, cnt);
    final_kernel<<<G_GRAPHS, 128>>>(pool, cnt, lin_w, lin_b, out);
}